// round 2
// baseline (speedup 1.0000x reference)
#include <cuda_runtime.h>
#include <math_constants.h>

// Problem constants
constexpr int NB = 8;     // batch
constexpr int NC = 512;   // channels
constexpr int NS = 1024;  // sequence (32*32)
constexpr int NH = 8;     // heads
constexpr int HD = 64;    // head dim

// Scratch for projected Q,K,V: [3][B][S][C] fp32 = 50.3 MB
__device__ float g_qkv[(size_t)3 * NB * NS * NC];

// ---------------------------------------------------------------------------
// Kernel A: QKV projection GEMM.
// out[z][b][s][n] = sum_k X[b][k][s] * W[k][z*512 + n] + bias[z*512+n]
// X is [B, C, S] so A-tile rows (fixed k, contiguous s) are coalesced.
// Block tile 64(M=s) x 64(N) x 16(K), 256 threads, 4x4 register blocking.
// grid = (8 Ntiles, 16 Mtiles, 24 = z*8+b)
// ---------------------------------------------------------------------------
__global__ __launch_bounds__(256) void qkv_gemm_kernel(
    const float* __restrict__ query, const float* __restrict__ kv,
    const float* __restrict__ W, const float* __restrict__ bias)
{
    __shared__ float As[16][64];
    __shared__ float Bs[16][64];

    const int zz = blockIdx.z >> 3;      // 0=q, 1=k, 2=v
    const int b  = blockIdx.z & 7;
    const int m0 = blockIdx.y * 64;
    const int n0 = blockIdx.x * 64;
    const float* __restrict__ X = (zz == 0) ? query : kv;
    const int colofs = zz * NC;

    const int t  = threadIdx.x;
    const int tx = t & 15, ty = t >> 4;
    const int lk = t >> 4;            // load row within K-tile (0..15)
    const int lm = (t & 15) * 4;      // load col (float4)

    const float* xb = X + (size_t)b * NC * NS;

    float acc[4][4] = {};
    for (int k0 = 0; k0 < NC; k0 += 16) {
        float4 av = *(const float4*)(xb + (size_t)(k0 + lk) * NS + m0 + lm);
        float4 bv = *(const float4*)(W + (size_t)(k0 + lk) * (3 * NC) + colofs + n0 + lm);
        __syncthreads();   // prior tile's compute done before overwrite
        *(float4*)&As[lk][lm] = av;
        *(float4*)&Bs[lk][lm] = bv;
        __syncthreads();
#pragma unroll
        for (int kk = 0; kk < 16; ++kk) {
            float4 a4 = *(const float4*)&As[kk][ty * 4];
            float4 b4 = *(const float4*)&Bs[kk][tx * 4];
            float aa[4] = {a4.x, a4.y, a4.z, a4.w};
            float bb[4] = {b4.x, b4.y, b4.z, b4.w};
#pragma unroll
            for (int i = 0; i < 4; ++i)
#pragma unroll
                for (int j = 0; j < 4; ++j)
                    acc[i][j] += aa[i] * bb[j];
        }
    }

    float4 bi = *(const float4*)(bias + colofs + n0 + tx * 4);
    float* outp = g_qkv + (size_t)(zz * NB + b) * NS * NC;
#pragma unroll
    for (int i = 0; i < 4; ++i) {
        const int m = m0 + ty * 4 + i;
        float4 v;
        v.x = acc[i][0] + bi.x;
        v.y = acc[i][1] + bi.y;
        v.z = acc[i][2] + bi.z;
        v.w = acc[i][3] + bi.w;
        *(float4*)(outp + (size_t)m * NC + n0 + tx * 4) = v;
    }
}

// ---------------------------------------------------------------------------
// Kernel B: flash-style attention. One block handles (b, h, 64 query rows).
// Streams K/V in 32-row tiles, online softmax. 256 threads = 64 rows x 4 lanes.
// Per thread: 8 score cols (c = g + 4j), 16 output dims (d = g*16 + j).
// Shared: Qs 64x68, Ks/Vs 32x68, Ps 64x36 -> 44 KB (fits static limit).
// grid = (16 qtiles, 8 heads, 8 batch)
// ---------------------------------------------------------------------------
__global__ __launch_bounds__(256) void attn_kernel(float* __restrict__ out)
{
    __shared__ float Qs[64][68];
    __shared__ float Ks[32][68];
    __shared__ float Vs[32][68];
    __shared__ float Ps[64][36];

    const int qt = blockIdx.x;
    const int h  = blockIdx.y;
    const int b  = blockIdx.z;
    const int t  = threadIdx.x;
    const int r  = t >> 2;     // query row within tile
    const int g  = t & 3;      // lane group
    const int s0 = qt * 64;
    const float scale = 0.125f;   // 64^-0.5

    const float* Qg = g_qkv + (size_t)(0 * NB + b) * NS * NC + h * HD;
    const float* Kg = g_qkv + (size_t)(1 * NB + b) * NS * NC + h * HD;
    const float* Vg = g_qkv + (size_t)(2 * NB + b) * NS * NC + h * HD;

    // Load Q tile (pre-scaled)
    {
        const int rr = t >> 2, d0 = (t & 3) * 16;
        const float* src = Qg + (size_t)(s0 + rr) * NC + d0;
#pragma unroll
        for (int k = 0; k < 16; k += 4) {
            float4 v = *(const float4*)(src + k);
            v.x *= scale; v.y *= scale; v.z *= scale; v.w *= scale;
            *(float4*)&Qs[rr][d0 + k] = v;
        }
    }

    float m = -CUDART_INF_F, l = 0.f;
    float4 o[4] = {};   // output acc: d = g*16 + (i*4 + component)

    const int lc = t >> 3, ld0 = (t & 7) * 8;  // K/V tile load mapping

    for (int kt = 0; kt < 32; ++kt) {
        const float* ksrc = Kg + (size_t)(kt * 32 + lc) * NC + ld0;
        const float* vsrc = Vg + (size_t)(kt * 32 + lc) * NC + ld0;
        float4 ka = *(const float4*)(ksrc);
        float4 kb = *(const float4*)(ksrc + 4);
        float4 va = *(const float4*)(vsrc);
        float4 vb = *(const float4*)(vsrc + 4);
        __syncthreads();   // prior iteration's P@V reads done
        *(float4*)&Ks[lc][ld0]     = ka;
        *(float4*)&Ks[lc][ld0 + 4] = kb;
        *(float4*)&Vs[lc][ld0]     = va;
        *(float4*)&Vs[lc][ld0 + 4] = vb;
        __syncthreads();

        // Scores for this thread's 8 columns
        float p[8] = {};
#pragma unroll
        for (int d4 = 0; d4 < 16; ++d4) {
            float4 q4 = *(const float4*)&Qs[r][d4 * 4];
#pragma unroll
            for (int j = 0; j < 8; ++j) {
                float4 k4 = *(const float4*)&Ks[g + 4 * j][d4 * 4];
                p[j] += q4.x * k4.x + q4.y * k4.y + q4.z * k4.z + q4.w * k4.w;
            }
        }

        // Online softmax update (reduce across the 4 lanes owning row r)
        float tmax = p[0];
#pragma unroll
        for (int j = 1; j < 8; ++j) tmax = fmaxf(tmax, p[j]);
        tmax = fmaxf(tmax, __shfl_xor_sync(0xffffffffu, tmax, 1));
        tmax = fmaxf(tmax, __shfl_xor_sync(0xffffffffu, tmax, 2));
        const float mn = fmaxf(m, tmax);
        const float alpha = __expf(m - mn);
        float tsum = 0.f;
#pragma unroll
        for (int j = 0; j < 8; ++j) { p[j] = __expf(p[j] - mn); tsum += p[j]; }
        tsum += __shfl_xor_sync(0xffffffffu, tsum, 1);
        tsum += __shfl_xor_sync(0xffffffffu, tsum, 2);
        l = l * alpha + tsum;
        m = mn;
#pragma unroll
        for (int i = 0; i < 4; ++i) {
            o[i].x *= alpha; o[i].y *= alpha; o[i].z *= alpha; o[i].w *= alpha;
        }
#pragma unroll
        for (int j = 0; j < 8; ++j) Ps[r][g + 4 * j] = p[j];
        __syncthreads();

        // O += P @ V  (this thread: all 32 cols, its 16 d's)
#pragma unroll
        for (int c4 = 0; c4 < 8; ++c4) {
            float4 p4 = *(const float4*)&Ps[r][c4 * 4];
            float pv[4] = {p4.x, p4.y, p4.z, p4.w};
#pragma unroll
            for (int cc = 0; cc < 4; ++cc) {
                const int c = c4 * 4 + cc;
#pragma unroll
                for (int i = 0; i < 4; ++i) {
                    float4 v4 = *(const float4*)&Vs[c][g * 16 + i * 4];
                    o[i].x += pv[cc] * v4.x;
                    o[i].y += pv[cc] * v4.y;
                    o[i].z += pv[cc] * v4.z;
                    o[i].w += pv[cc] * v4.w;
                }
            }
        }
        // next iteration's first __syncthreads protects Ks/Vs/Ps
    }

    const float inv = 1.f / l;
#pragma unroll
    for (int i = 0; i < 4; ++i) {
        o[i].x *= inv; o[i].y *= inv; o[i].z *= inv; o[i].w *= inv;
    }

    // Stage O^T through shared (reuse Qs as [d][r]) for coalesced [B,C,S] store
    __syncthreads();
#pragma unroll
    for (int i = 0; i < 4; ++i) {
        Qs[g * 16 + i * 4 + 0][r] = o[i].x;
        Qs[g * 16 + i * 4 + 1][r] = o[i].y;
        Qs[g * 16 + i * 4 + 2][r] = o[i].z;
        Qs[g * 16 + i * 4 + 3][r] = o[i].w;
    }
    __syncthreads();

    const int d = t >> 2, r0 = (t & 3) * 16;
    float* dst = out + (size_t)b * NC * NS + (size_t)(h * HD + d) * NS + s0 + r0;
#pragma unroll
    for (int k = 0; k < 16; k += 4) {
        float4 v;
        v.x = Qs[d][r0 + k + 0];
        v.y = Qs[d][r0 + k + 1];
        v.z = Qs[d][r0 + k + 2];
        v.w = Qs[d][r0 + k + 3];
        *(float4*)(dst + k) = v;
    }
}

// ---------------------------------------------------------------------------
extern "C" void kernel_launch(void* const* d_in, const int* in_sizes, int n_in,
                              void* d_out, int out_size)
{
    (void)in_sizes; (void)n_in; (void)out_size;
    const float* query = (const float*)d_in[0];
    const float* kv    = (const float*)d_in[1];
    const float* W     = (const float*)d_in[2];
    const float* bias  = (const float*)d_in[3];
    float* out = (float*)d_out;

    dim3 gA(NC / 64, NS / 64, 3 * NB);   // (8, 16, 24)
    qkv_gemm_kernel<<<gA, 256>>>(query, kv, W, bias);

    dim3 gB(NS / 64, NH, NB);            // (16, 8, 8)
    attn_kernel<<<gB, 256>>>(out);
}

// round 4
// speedup vs baseline: 2.9098x; 2.9098x over previous
#include <cuda_runtime.h>
#include <math_constants.h>
#include <cstdint>

constexpr int NB=8, NC=512, NS=1024, NH=8, HD=64;
__device__ float g_qkv[(size_t)3*NB*NS*NC];   // [z][b][s][NC]

__device__ __forceinline__ float tf32r(float x){ float r; asm("cvt.rna.tf32.f32 %0, %1;":"=f"(r):"f"(x)); return r; }
__device__ __forceinline__ uint32_t fu(float x){ return __float_as_uint(x); }
__device__ __forceinline__ void mma8(float* c, uint32_t a0,uint32_t a1,uint32_t a2,uint32_t a3,
                                     uint32_t b0,uint32_t b1){
    asm volatile("mma.sync.aligned.m16n8k8.row.col.f32.tf32.tf32.f32 "
                 "{%0,%1,%2,%3}, {%4,%5,%6,%7}, {%8,%9}, {%0,%1,%2,%3};"
                 : "+f"(c[0]),"+f"(c[1]),"+f"(c[2]),"+f"(c[3])
                 : "r"(a0),"r"(a1),"r"(a2),"r"(a3),"r"(b0),"r"(b1));
}

// ---------------------------------------------------------------------------
// Kernel A: QKV projection. C[m=1024][n=512] = X^T W (+bias) per (z,b).
// Block tile 128x64, K-chunk 32. 256 thr = 8 warps (4M x 2N), warp tile 32x32.
// As[m][k] stride 36, Bs[n][k] stride 36 -> conflict-free fragment LDS.
// grid (8 Ntile, 8 Mtile, 24 = z*8+b)
// ---------------------------------------------------------------------------
__global__ __launch_bounds__(256) void qkv_gemm_mma(
    const float* __restrict__ query, const float* __restrict__ kv,
    const float* __restrict__ W, const float* __restrict__ bias)
{
    __shared__ float As[128*36];
    __shared__ float Bs[64*36];

    const int t = threadIdx.x, w = t>>5, g = (t&31)>>2, q = t&3;
    const int wm = (w&3)*32, wn = (w>>2)*32;
    const int zz = blockIdx.z>>3, b = blockIdx.z&7;
    const int m0 = blockIdx.y*128, n0 = blockIdx.x*64, colofs = zz*NC;
    const float* __restrict__ X = (zz==0)?query:kv;
    const float* xb = X + (size_t)b*NC*NS;

    float acc[2][4][4] = {};

    const int am = t&127, ak = t>>7;      // A loader: m, k-offset (0/1)
    const int bn = t&63,  bk = t>>6;      // B loader: n, k-offset (0..3)

    for (int c=0; c<16; ++c){
        const int k0 = c*32;
        __syncthreads();
#pragma unroll
        for (int kk=0; kk<16; ++kk){
            const int k = kk*2 + ak;
            As[am*36+k] = tf32r(xb[(size_t)(k0+k)*NS + m0 + am]);
        }
#pragma unroll
        for (int kk=0; kk<8; ++kk){
            const int k = kk*4 + bk;
            Bs[bn*36+k] = tf32r(W[(size_t)(k0+k)*(3*NC) + colofs + n0 + bn]);
        }
        __syncthreads();
#pragma unroll
        for (int ks=0; ks<4; ++ks){
            const int kb = ks*8 + q;
            uint32_t a[2][4], bb[4][2];
#pragma unroll
            for (int mi=0; mi<2; ++mi){
                const int r = wm + mi*16 + g;
                a[mi][0] = fu(As[r*36+kb]);
                a[mi][1] = fu(As[(r+8)*36+kb]);
                a[mi][2] = fu(As[r*36+kb+4]);
                a[mi][3] = fu(As[(r+8)*36+kb+4]);
            }
#pragma unroll
            for (int ni=0; ni<4; ++ni){
                const int n = wn + ni*8 + g;
                bb[ni][0] = fu(Bs[n*36+kb]);
                bb[ni][1] = fu(Bs[n*36+kb+4]);
            }
#pragma unroll
            for (int mi=0; mi<2; ++mi)
#pragma unroll
                for (int ni=0; ni<4; ++ni)
                    mma8(acc[mi][ni], a[mi][0],a[mi][1],a[mi][2],a[mi][3], bb[ni][0],bb[ni][1]);
        }
    }

    float* outp = g_qkv + (size_t)(zz*NB+b)*NS*NC;
#pragma unroll
    for (int mi=0; mi<2; ++mi)
#pragma unroll
        for (int ni=0; ni<4; ++ni){
            const int m = m0 + wm + mi*16 + g;
            const int n = n0 + wn + ni*8 + q*2;
            const float bi0 = bias[colofs+n], bi1 = bias[colofs+n+1];
            *(float2*)(outp + (size_t)m*NC + n)     = make_float2(acc[mi][ni][0]+bi0, acc[mi][ni][1]+bi1);
            *(float2*)(outp + (size_t)(m+8)*NC + n) = make_float2(acc[mi][ni][2]+bi0, acc[mi][ni][3]+bi1);
        }
}

// ---------------------------------------------------------------------------
// Kernel B: flash attention on mma.sync. grid (8 qtile, 8 h, 8 b), 256 thr.
// Warp w owns q-rows [w*16, w*16+16). kv tile 64. Online softmax per 4-lane quad.
// smem (dyn, stride 68): Qs 128x68 | Ks 64x68 | VT 64x68 | Ps 128x68 = 102KB
// ---------------------------------------------------------------------------
__global__ __launch_bounds__(256) void attn_mma(float* __restrict__ out)
{
    extern __shared__ float sm[];
    float* Qs = sm;                 // 128*68
    float* Ks = Qs + 128*68;        // 64*68
    float* VT = Ks + 64*68;         // 64*68
    float* Ps = VT + 64*68;         // 128*68

    const int t = threadIdx.x, w = t>>5, g = (t&31)>>2, q = t&3;
    const int qt = blockIdx.x, h = blockIdx.y, b = blockIdx.z;
    const int s0 = qt*128, wr = w*16;

    const float* Qg = g_qkv + ((size_t)(0*NB+b)*NS + s0)*NC + h*HD;
    const float* Kg = g_qkv + ((size_t)(1*NB+b)*NS)*NC + h*HD;
    const float* Vg = g_qkv + ((size_t)(2*NB+b)*NS)*NC + h*HD;

    // Q tile [128][64], pre-scaled, tf32
    {
        const int m = t&127, dh = (t>>7)*32;
#pragma unroll
        for (int j=0; j<32; ++j)
            Qs[m*68 + dh + j] = tf32r(Qg[(size_t)m*NC + dh + j] * 0.125f);
    }

    float mrow[2] = {-CUDART_INF_F, -CUDART_INF_F};
    float lrow[2] = {0.f, 0.f};
    float O[8][4] = {};

    const int kr = t&63, kd = (t>>6)*16;   // K/V loader mapping

    for (int it=0; it<16; ++it){
        const int c0 = it*64;
#pragma unroll
        for (int j=0; j<16; ++j)
            Ks[kr*68 + kd + j] = tf32r(Kg[(size_t)(c0+kr)*NC + kd + j]);
#pragma unroll
        for (int j=0; j<16; ++j)
            VT[(kd+j)*68 + kr] = tf32r(Vg[(size_t)(c0+kr)*NC + kd + j]);
        __syncthreads();

        // S = Q K^T : warp tile 16x64
        float s[8][4] = {};
#pragma unroll
        for (int ks=0; ks<8; ++ks){
            const int kb = ks*8 + q;
            const uint32_t a0 = fu(Qs[(wr+g)*68+kb]),   a1 = fu(Qs[(wr+g+8)*68+kb]);
            const uint32_t a2 = fu(Qs[(wr+g)*68+kb+4]), a3 = fu(Qs[(wr+g+8)*68+kb+4]);
#pragma unroll
            for (int ni=0; ni<8; ++ni){
                const uint32_t b0 = fu(Ks[(ni*8+g)*68+kb]), b1 = fu(Ks[(ni*8+g)*68+kb+4]);
                mma8(s[ni], a0,a1,a2,a3, b0,b1);
            }
        }

        // online softmax (rows wr+g and wr+g+8)
        float mx0 = mrow[0], mx1 = mrow[1];
#pragma unroll
        for (int ni=0; ni<8; ++ni){
            mx0 = fmaxf(mx0, fmaxf(s[ni][0], s[ni][1]));
            mx1 = fmaxf(mx1, fmaxf(s[ni][2], s[ni][3]));
        }
        mx0 = fmaxf(mx0, __shfl_xor_sync(0xffffffffu, mx0, 1));
        mx0 = fmaxf(mx0, __shfl_xor_sync(0xffffffffu, mx0, 2));
        mx1 = fmaxf(mx1, __shfl_xor_sync(0xffffffffu, mx1, 1));
        mx1 = fmaxf(mx1, __shfl_xor_sync(0xffffffffu, mx1, 2));
        const float al0 = __expf(mrow[0]-mx0), al1 = __expf(mrow[1]-mx1);
        float sum0 = 0.f, sum1 = 0.f;
#pragma unroll
        for (int ni=0; ni<8; ++ni){
            s[ni][0] = __expf(s[ni][0]-mx0); s[ni][1] = __expf(s[ni][1]-mx0);
            s[ni][2] = __expf(s[ni][2]-mx1); s[ni][3] = __expf(s[ni][3]-mx1);
            sum0 += s[ni][0] + s[ni][1];
            sum1 += s[ni][2] + s[ni][3];
        }
        sum0 += __shfl_xor_sync(0xffffffffu, sum0, 1);
        sum0 += __shfl_xor_sync(0xffffffffu, sum0, 2);
        sum1 += __shfl_xor_sync(0xffffffffu, sum1, 1);
        sum1 += __shfl_xor_sync(0xffffffffu, sum1, 2);
        lrow[0] = lrow[0]*al0 + sum0;  mrow[0] = mx0;
        lrow[1] = lrow[1]*al1 + sum1;  mrow[1] = mx1;
#pragma unroll
        for (int ni=0; ni<8; ++ni){
            O[ni][0] *= al0; O[ni][1] *= al0;
            O[ni][2] *= al1; O[ni][3] *= al1;
        }

        // P -> smem (tf32), warp-private rows
#pragma unroll
        for (int ni=0; ni<8; ++ni){
            const int cc = ni*8 + q*2;
            *(float2*)&Ps[(wr+g)*68 + cc]   = make_float2(tf32r(s[ni][0]), tf32r(s[ni][1]));
            *(float2*)&Ps[(wr+g+8)*68 + cc] = make_float2(tf32r(s[ni][2]), tf32r(s[ni][3]));
        }
        __syncwarp();

        // O += P @ V
#pragma unroll
        for (int ks=0; ks<8; ++ks){
            const int kb = ks*8 + q;
            const uint32_t a0 = fu(Ps[(wr+g)*68+kb]),   a1 = fu(Ps[(wr+g+8)*68+kb]);
            const uint32_t a2 = fu(Ps[(wr+g)*68+kb+4]), a3 = fu(Ps[(wr+g+8)*68+kb+4]);
#pragma unroll
            for (int ni=0; ni<8; ++ni){
                const uint32_t b0 = fu(VT[(ni*8+g)*68+kb]), b1 = fu(VT[(ni*8+g)*68+kb+4]);
                mma8(O[ni], a0,a1,a2,a3, b0,b1);
            }
        }
        __syncthreads();   // before next iter's K/VT overwrite
    }

    // normalize + stage O^T via Qs, coalesced store to [B,C,S]
    const float inv0 = 1.f/lrow[0], inv1 = 1.f/lrow[1];
#pragma unroll
    for (int ni=0; ni<8; ++ni){
        const int cc = ni*8 + q*2;
        *(float2*)&Qs[(wr+g)*68 + cc]   = make_float2(O[ni][0]*inv0, O[ni][1]*inv0);
        *(float2*)&Qs[(wr+g+8)*68 + cc] = make_float2(O[ni][2]*inv1, O[ni][3]*inv1);
    }
    __syncthreads();
    const int d = t>>2, sq = (t&3)*32;
    float* dst = out + ((size_t)b*NC + h*HD + d)*NS + s0 + sq;
#pragma unroll
    for (int j=0; j<32; j+=4){
        float4 v;
        v.x = Qs[(sq+j+0)*68 + d];
        v.y = Qs[(sq+j+1)*68 + d];
        v.z = Qs[(sq+j+2)*68 + d];
        v.w = Qs[(sq+j+3)*68 + d];
        *(float4*)(dst+j) = v;
    }
}

// ---------------------------------------------------------------------------
extern "C" void kernel_launch(void* const* d_in, const int* in_sizes, int n_in,
                              void* d_out, int out_size)
{
    (void)in_sizes; (void)n_in; (void)out_size;
    const float* query = (const float*)d_in[0];
    const float* kv    = (const float*)d_in[1];
    const float* W     = (const float*)d_in[2];
    const float* bias  = (const float*)d_in[3];
    float* out = (float*)d_out;

    const int asm_bytes = (128+64+64+128)*68*4;   // 104448
    cudaFuncSetAttribute(attn_mma, cudaFuncAttributeMaxDynamicSharedMemorySize, asm_bytes);

    dim3 gA(8, 8, 24);
    qkv_gemm_mma<<<gA, 256>>>(query, kv, W, bias);
    dim3 gB(8, NH, NB);
    attn_mma<<<gB, 256, asm_bytes>>>(out);
}